// round 4
// baseline (speedup 1.0000x reference)
#include <cuda_runtime.h>
#include <math_constants.h>

// Problem constants
constexpr int B = 32, S = 4, K = 11, C = 9, H = 128, W = 128;
constexpr int HW = H * W;           // 16384
constexpr int BK = B * K;           // 352 (b,k) tiles
constexpr int BS = B * S;           // 128
constexpr int P = 4;                // plane splits -> grid = 1408 blocks
constexpr int CHUNK = HW / 4 / P;   // 1024 float4s per block

// Cross-block scratch (device globals: no allocation allowed)
__device__ float              g_sqp[BK * S * P];  // sumsq partials
__device__ unsigned long long g_amax[BK * S];     // packed (key | ~idx) argmax
__device__ int                g_count[BK];        // arrival counter per (b,k)

// orderable-float key: monotone map float -> uint32 (total order)
__device__ __forceinline__ unsigned int fkey(float v) {
    unsigned int u = __float_as_uint(v);
    return (u & 0x80000000u) ? ~u : (u | 0x80000000u);
}
__device__ __forceinline__ float fkey_inv(unsigned int key) {
    unsigned int u = (key & 0x80000000u) ? (key & 0x7FFFFFFFu) : ~key;
    return __uint_as_float(u);
}

// Zero scratch + output every launch (graph-replay safe).
__global__ __launch_bounds__(256) void kp_zero_kernel(float* __restrict__ out) {
    const int t = blockIdx.x * 256 + threadIdx.x;
    if (t < 2 * BS)  out[t] = 0.0f;
    if (t < BK)      g_count[t] = 0;
    if (t < BK * S)  g_amax[t] = 0ULL;
}

// grid = P * BK blocks. Block (part, bk) streams CHUNK float4s of the
// heatmap plane once against all S=4 pred planes. Last-arriving block per
// (b,k) runs the fused label-loss epilogue.
__global__ __launch_bounds__(256) void kp_fused_kernel(
    const float* __restrict__ hm_preds,   // [B,S,K,H,W]
    const float* __restrict__ lb_preds,   // [B,S,C,H,W]
    const float* __restrict__ heatmaps,   // [B,K,H,W]
    const float* __restrict__ labels,     // [B,K,11]
    float* __restrict__ out)              // [2*B*S]: [hm | lb]
{
    const int bid  = blockIdx.x;
    const int bk   = bid % BK;            // (b,k) tile
    const int part = bid / BK;            // plane chunk
    const int k = bk % K;
    const int b = bk / K;

    const float4* __restrict__ g =
        reinterpret_cast<const float4*>(heatmaps + ((size_t)b * K + k) * HW);
    const float4* __restrict__ p0 =
        reinterpret_cast<const float4*>(hm_preds + ((size_t)b * S * K + k) * HW);
    constexpr size_t SSTRIDE = (size_t)K * HW / 4;   // float4 stride between s

    const int tid = threadIdx.x;

    float sq[S];
    float mx[S];
    int   mi[S];
    #pragma unroll
    for (int s = 0; s < S; s++) { sq[s] = 0.0f; mx[s] = -CUDART_INF_F; mi[s] = 0; }

    const int i0 = part * CHUNK;
    // CHUNK/256 = 4 iterations per thread, 5 independent LDG.128 each
    #pragma unroll
    for (int it = 0; it < CHUNK / 256; it++) {
        const int i = i0 + it * 256 + tid;
        const float4 gv = __ldcs(&g[i]);
        const int base = i * 4;
        #pragma unroll
        for (int s = 0; s < S; s++) {
            const float4 pv = __ldcs(&p0[(size_t)s * SSTRIDE + i]);
            float d0 = pv.x - gv.x, d1 = pv.y - gv.y;
            float d2 = pv.z - gv.z, d3 = pv.w - gv.w;
            sq[s] += d0 * d0 + d1 * d1 + d2 * d2 + d3 * d3;
            if (pv.x > mx[s]) { mx[s] = pv.x; mi[s] = base;     }
            if (pv.y > mx[s]) { mx[s] = pv.y; mi[s] = base + 1; }
            if (pv.z > mx[s]) { mx[s] = pv.z; mi[s] = base + 2; }
            if (pv.w > mx[s]) { mx[s] = pv.w; mi[s] = base + 3; }
        }
    }

    // Per-warp reduction (sum + argmax, first-index tiebreak)
    #pragma unroll
    for (int s = 0; s < S; s++) {
        #pragma unroll
        for (int off = 16; off > 0; off >>= 1) {
            sq[s] += __shfl_down_sync(0xFFFFFFFFu, sq[s], off);
            float omx = __shfl_down_sync(0xFFFFFFFFu, mx[s], off);
            int   omi = __shfl_down_sync(0xFFFFFFFFu, mi[s], off);
            if (omx > mx[s] || (omx == mx[s] && omi < mi[s])) {
                mx[s] = omx; mi[s] = omi;
            }
        }
    }

    __shared__ float s_sq[S][8];
    __shared__ float s_mx[S][8];
    __shared__ int   s_mi[S][8];
    __shared__ int   s_last;
    const int wid = tid >> 5, lane = tid & 31;
    if (lane == 0) {
        #pragma unroll
        for (int s = 0; s < S; s++) {
            s_sq[s][wid] = sq[s];
            s_mx[s][wid] = mx[s];
            s_mi[s][wid] = mi[s];
        }
    }
    __syncthreads();

    // Warps 0..3: finish block-level result for stack s = wid, publish.
    if (wid < S) {
        const int s = wid;
        float fsq = (lane < 8) ? s_sq[s][lane] : 0.0f;
        float fmx = (lane < 8) ? s_mx[s][lane] : -CUDART_INF_F;
        int   fmi = (lane < 8) ? s_mi[s][lane] : 0x7FFFFFFF;
        #pragma unroll
        for (int off = 4; off > 0; off >>= 1) {
            fsq += __shfl_down_sync(0xFFFFFFFFu, fsq, off);
            float omx = __shfl_down_sync(0xFFFFFFFFu, fmx, off);
            int   omi = __shfl_down_sync(0xFFFFFFFFu, fmi, off);
            if (omx > fmx || (omx == fmx && omi < fmi)) { fmx = omx; fmi = omi; }
        }
        if (lane == 0) {
            g_sqp[((size_t)bk * S + s) * P + part] = fsq;
            const unsigned long long packed =
                ((unsigned long long)fkey(fmx) << 32) |
                (unsigned long long)(0xFFFFFFFFu - (unsigned int)fmi);
            atomicMax(&g_amax[bk * S + s], packed);
            __threadfence();   // publish before the counter bump
        }
    }
    __syncthreads();

    if (tid == 0) {
        const int old = atomicAdd(&g_count[bk], 1);
        s_last = (old == P - 1);
    }
    __syncthreads();
    if (!s_last) return;

    // ---- Last block for this (b,k): fused epilogue, warp per stack ----
    if (wid < S) {
        const int s = wid;
        const int bs = b * S + s;

        float fsq = 0.0f;
        #pragma unroll
        for (int p = 0; p < P; p++)
            fsq += __ldcg(&g_sqp[((size_t)bk * S + s) * P + p]);

        const unsigned long long packed = __ldcg(&g_amax[bk * S + s]);
        const float conf = fkey_inv((unsigned int)(packed >> 32));
        const int   fmi  = (int)(0xFFFFFFFFu - (unsigned int)packed);

        const float* __restrict__ lab = labels + ((size_t)b * K + k) * 11;

        float part9 = 0.0f;
        if (lane < C) {
            const float v = __ldg(&lb_preds[((size_t)bs * C + lane) * HW + fmi]);
            const float d = v - __ldg(&lab[lane]);
            part9 = d * d;
        }
        #pragma unroll
        for (int off = 8; off > 0; off >>= 1)
            part9 += __shfl_down_sync(0xFFFFFFFFu, part9, off);

        if (lane == 0) {
            const float gx = __ldg(&lab[9]);
            const float gy = __ldg(&lab[10]);
            const bool valid = (gx >= 0.0f) && (gy >= 0.0f) &&
                               (gx < (float)H) && (gy < (float)W);
            const int x = fmi / W;   // H == W == 128: pos == idx
            const int y = fmi % W;
            const float dx = gx - (float)x;
            const float dy = gy - (float)y;
            const float cf = 1.0f - conf;
            const float lb = valid ? (part9 + dx * dx + dy * dy + cf * cf) : 0.0f;

            atomicAdd(&out[bs],      fsq);  // hm_loss [B,S]
            atomicAdd(&out[BS + bs], lb);   // lb_loss [B,S]
        }
    }
}

extern "C" void kernel_launch(void* const* d_in, const int* in_sizes, int n_in,
                              void* d_out, int out_size) {
    const float* hm_preds = (const float*)d_in[0];  // [B,S,K,H,W]
    const float* lb_preds = (const float*)d_in[1];  // [B,S,C,H,W]
    const float* heatmaps = (const float*)d_in[2];  // [B,K,H,W]
    const float* labels   = (const float*)d_in[3];  // [B,K,11]
    float* out = (float*)d_out;

    kp_zero_kernel<<<(BK * S + 255) / 256 + 1, 256>>>(out);
    kp_fused_kernel<<<P * BK, 256>>>(hm_preds, lb_preds, heatmaps, labels, out);
}

// round 5
// speedup vs baseline: 1.0837x; 1.0837x over previous
#include <cuda_runtime.h>
#include <math_constants.h>

// Problem constants
constexpr int B = 32, S = 4, K = 11, C = 9, H = 128, W = 128;
constexpr int HW = 16384;
constexpr int BK = B * K;            // 352 (b,k) tiles
constexpr int BS = B * S;            // 128
constexpr int P = 4;                 // plane splits -> grid = 1408
constexpr int CHUNK4 = HW / 4 / P;   // 1024 float4s (16 KB) per block

// Cross-block scratch (device globals: no allocation allowed)
__device__ unsigned long long g_amax[BK * S];  // packed (key | ~idx) argmax
__device__ int                g_count[BK];     // arrival counter per (b,k)

// orderable-float key: monotone map float -> uint32 (total order)
__device__ __forceinline__ unsigned int fkey(float v) {
    unsigned int u = __float_as_uint(v);
    return (u & 0x80000000u) ? ~u : (u | 0x80000000u);
}
__device__ __forceinline__ float fkey_inv(unsigned int key) {
    unsigned int u = (key & 0x80000000u) ? (key & 0x7FFFFFFFu) : ~key;
    return __uint_as_float(u);
}

// Zero scratch + output every launch (graph-replay safe).
__global__ __launch_bounds__(256) void kp_zero_kernel(float* __restrict__ out) {
    const int t = blockIdx.x * 256 + threadIdx.x;
    if (t < 2 * BS)  out[t] = 0.0f;
    if (t < BK)      g_count[t] = 0;
    if (t < BK * S)  g_amax[t] = 0ULL;
}

// grid = BK*P. Block (bk, part): stage heatmap chunk in smem once, then 4
// sequential passes (one per stack) over the pred planes. Last block per
// (b,k) runs the label-loss epilogue.
__global__ __launch_bounds__(256) void kp_fused_kernel(
    const float* __restrict__ hm_preds,   // [B,S,K,H,W]
    const float* __restrict__ lb_preds,   // [B,S,C,H,W]
    const float* __restrict__ heatmaps,   // [B,K,H,W]
    const float* __restrict__ labels,     // [B,K,11]
    float* __restrict__ out)              // [2*B*S]: [hm | lb]
{
    const int bid  = blockIdx.x;
    const int bk   = bid / P;             // (b,k) tile
    const int part = bid % P;             // plane chunk (adjacent bids adjacent)
    const int k = bk % K;
    const int b = bk / K;

    __shared__ float4 sg[CHUNK4];         // 16 KB heatmap chunk
    __shared__ float  s_sq[8];
    __shared__ float  s_mx[8];
    __shared__ int    s_mi[8];
    __shared__ int    s_last;

    const float4* __restrict__ g =
        reinterpret_cast<const float4*>(heatmaps + ((size_t)b * K + k) * HW);
    const float4* __restrict__ p0 =
        reinterpret_cast<const float4*>(hm_preds + ((size_t)b * S * K + k) * HW);
    constexpr size_t SSTRIDE = (size_t)K * HW / 4;   // float4 stride between s

    const int tid = threadIdx.x;
    const int wid = tid >> 5, lane = tid & 31;
    const int i0 = part * CHUNK4;

    // Stage heatmap chunk (read from global exactly once per element, total)
    #pragma unroll
    for (int it = 0; it < CHUNK4 / 256; it++) {
        const int il = it * 256 + tid;
        sg[il] = __ldcs(&g[i0 + il]);
    }
    __syncthreads();

    #pragma unroll 1
    for (int s = 0; s < S; s++) {
        const float4* __restrict__ ps = p0 + (size_t)s * SSTRIDE;

        // Batch all 4 global loads up front (MLP)
        float4 pv[CHUNK4 / 256];
        #pragma unroll
        for (int it = 0; it < CHUNK4 / 256; it++)
            pv[it] = __ldcs(&ps[i0 + it * 256 + tid]);

        float sq = 0.0f;
        float mx = -CUDART_INF_F;
        int   mi = 0;
        #pragma unroll
        for (int it = 0; it < CHUNK4 / 256; it++) {
            const int il = it * 256 + tid;
            const float4 gv = sg[il];
            const float4 pp = pv[it];
            float d0 = pp.x - gv.x, d1 = pp.y - gv.y;
            float d2 = pp.z - gv.z, d3 = pp.w - gv.w;
            sq += d0 * d0 + d1 * d1 + d2 * d2 + d3 * d3;
            const int base = (i0 + il) * 4;
            // strict > keeps lowest index within this thread (ascending scan)
            if (pp.x > mx) { mx = pp.x; mi = base;     }
            if (pp.y > mx) { mx = pp.y; mi = base + 1; }
            if (pp.z > mx) { mx = pp.z; mi = base + 2; }
            if (pp.w > mx) { mx = pp.w; mi = base + 3; }
        }

        // Warp reduce (sum + argmax first-index tiebreak)
        #pragma unroll
        for (int off = 16; off > 0; off >>= 1) {
            sq += __shfl_down_sync(0xFFFFFFFFu, sq, off);
            float omx = __shfl_down_sync(0xFFFFFFFFu, mx, off);
            int   omi = __shfl_down_sync(0xFFFFFFFFu, mi, off);
            if (omx > mx || (omx == mx && omi < mi)) { mx = omx; mi = omi; }
        }
        if (lane == 0) { s_sq[wid] = sq; s_mx[wid] = mx; s_mi[wid] = mi; }
        __syncthreads();

        if (wid == 0) {
            sq = (lane < 8) ? s_sq[lane] : 0.0f;
            mx = (lane < 8) ? s_mx[lane] : -CUDART_INF_F;
            mi = (lane < 8) ? s_mi[lane] : 0x7FFFFFFF;
            #pragma unroll
            for (int off = 4; off > 0; off >>= 1) {
                sq += __shfl_down_sync(0xFFFFFFFFu, sq, off);
                float omx = __shfl_down_sync(0xFFFFFFFFu, mx, off);
                int   omi = __shfl_down_sync(0xFFFFFFFFu, mi, off);
                if (omx > mx || (omx == mx && omi < mi)) { mx = omx; mi = omi; }
            }
            if (lane == 0) {
                atomicAdd(&out[b * S + s], sq);     // hm_loss partial
                const unsigned long long packed =
                    ((unsigned long long)fkey(mx) << 32) |
                    (unsigned long long)(0xFFFFFFFFu - (unsigned int)mi);
                atomicMax(&g_amax[bk * S + s], packed);
            }
        }
        __syncthreads();   // staging reuse next s
    }

    // Arrival counter: last block of this (b,k) runs the label epilogue
    if (tid == 0) {
        __threadfence();
        const int old = atomicAdd(&g_count[bk], 1);
        s_last = (old == P - 1);
    }
    __syncthreads();
    if (!s_last) return;
    __threadfence();   // acquire published g_amax

    if (wid < S) {
        const int s = wid;
        const int bs = b * S + s;

        const unsigned long long packed = __ldcg(&g_amax[bk * S + s]);
        const float conf = fkey_inv((unsigned int)(packed >> 32));
        const int   fmi  = (int)(0xFFFFFFFFu - (unsigned int)packed);

        const float* __restrict__ lab = labels + ((size_t)b * K + k) * 11;

        float part9 = 0.0f;
        if (lane < C) {
            const float v = __ldg(&lb_preds[((size_t)bs * C + lane) * HW + fmi]);
            const float d = v - __ldg(&lab[lane]);
            part9 = d * d;
        }
        #pragma unroll
        for (int off = 8; off > 0; off >>= 1)
            part9 += __shfl_down_sync(0xFFFFFFFFu, part9, off);

        if (lane == 0) {
            const float gx = __ldg(&lab[9]);
            const float gy = __ldg(&lab[10]);
            const bool valid = (gx >= 0.0f) && (gy >= 0.0f) &&
                               (gx < (float)H) && (gy < (float)W);
            const int x = fmi / W;   // H == W == 128: pos == idx
            const int y = fmi % W;
            const float dx = gx - (float)x;
            const float dy = gy - (float)y;
            const float cf = 1.0f - conf;
            const float lb = valid ? (part9 + dx * dx + dy * dy + cf * cf) : 0.0f;
            atomicAdd(&out[BS + bs], lb);   // lb_loss [B,S]
        }
    }
}

extern "C" void kernel_launch(void* const* d_in, const int* in_sizes, int n_in,
                              void* d_out, int out_size) {
    const float* hm_preds = (const float*)d_in[0];  // [B,S,K,H,W]
    const float* lb_preds = (const float*)d_in[1];  // [B,S,C,H,W]
    const float* heatmaps = (const float*)d_in[2];  // [B,K,H,W]
    const float* labels   = (const float*)d_in[3];  // [B,K,11]
    float* out = (float*)d_out;

    kp_zero_kernel<<<(BK * S + 255) / 256, 256>>>(out);
    kp_fused_kernel<<<BK * P, 256>>>(hm_preds, lb_preds, heatmaps, labels, out);
}

// round 6
// speedup vs baseline: 1.1722x; 1.0816x over previous
#include <cuda_runtime.h>
#include <math_constants.h>

// Problem constants
constexpr int B = 32, S = 4, K = 11, C = 9, H = 128, W = 128;
constexpr int HW = H * W;          // 16384
constexpr int BSK = B * S * K;     // 1408
constexpr int BS = B * S;          // 128

// Zero-init the output (poisoned by harness; we accumulate with atomics).
__global__ __launch_bounds__(256) void kp_zero_kernel(float* __restrict__ out) {
    out[threadIdx.x] = 0.0f;       // exactly 2*BS = 256 elements
}

// One block per (b,s,k): fused squared-diff reduction + argmax + label-loss
// epilogue. Loads batched 8-deep (4 pred + 4 gt LDG.128) for MLP; 4 sumsq
// accumulators + 2 argmax chains to shorten dependency chains.
__global__ __launch_bounds__(256) void kp_fused_kernel(
    const float* __restrict__ hm_preds,   // [B,S,K,H,W]
    const float* __restrict__ lb_preds,   // [B,S,C,H,W]
    const float* __restrict__ heatmaps,   // [B,K,H,W]
    const float* __restrict__ labels,     // [B,K,11]
    float* __restrict__ out)              // [2*B*S]: [hm | lb]
{
    const int blk = blockIdx.x;           // b*S*K + s*K + k
    const int k = blk % K;
    const int bs = blk / K;               // b*S + s
    const int b = bs / S;

    const float4* __restrict__ p =
        reinterpret_cast<const float4*>(hm_preds + (size_t)blk * HW);
    const float4* __restrict__ g =
        reinterpret_cast<const float4*>(heatmaps + ((size_t)b * K + k) * HW);

    const int tid = threadIdx.x;

    float sq0 = 0.0f, sq1 = 0.0f, sq2 = 0.0f, sq3 = 0.0f;
    float mxa = -CUDART_INF_F, mxb = -CUDART_INF_F;
    int   mia = 0,             mib = 0;

    // 4096 float4s / 256 threads = 16 iters, in 4 groups of 4.
    // Each group: 8 independent LDG.128 issued before any use.
    #pragma unroll 1
    for (int grp = 0; grp < 4; grp++) {
        const int ibase = grp * 1024 + tid;

        float4 pv[4], gv[4];
        #pragma unroll
        for (int j = 0; j < 4; j++) pv[j] = __ldcs(&p[ibase + j * 256]);
        #pragma unroll
        for (int j = 0; j < 4; j++) gv[j] = __ldg(&g[ibase + j * 256]);

        #pragma unroll
        for (int j = 0; j < 4; j++) {
            const float4 pp = pv[j];
            const float4 gg = gv[j];
            float d0 = pp.x - gg.x, d1 = pp.y - gg.y;
            float d2 = pp.z - gg.z, d3 = pp.w - gg.w;
            sq0 += d0 * d0; sq1 += d1 * d1;
            sq2 += d2 * d2; sq3 += d3 * d3;
            const int base = (ibase + j * 256) * 4;
            if (j < 2) {   // chain A: j = 0,1 (indices ascend within chain)
                if (pp.x > mxa) { mxa = pp.x; mia = base;     }
                if (pp.y > mxa) { mxa = pp.y; mia = base + 1; }
                if (pp.z > mxa) { mxa = pp.z; mia = base + 2; }
                if (pp.w > mxa) { mxa = pp.w; mia = base + 3; }
            } else {       // chain B: j = 2,3
                if (pp.x > mxb) { mxb = pp.x; mib = base;     }
                if (pp.y > mxb) { mxb = pp.y; mib = base + 1; }
                if (pp.z > mxb) { mxb = pp.z; mib = base + 2; }
                if (pp.w > mxb) { mxb = pp.w; mib = base + 3; }
            }
        }
    }

    // Merge chains (first-index tiebreak) and sumsq accumulators
    float sq = (sq0 + sq1) + (sq2 + sq3);
    float mx = mxa; int mi = mia;
    if (mxb > mx || (mxb == mx && mib < mi)) { mx = mxb; mi = mib; }

    // Warp reduction (sum + argmax with first-index tiebreak)
    #pragma unroll
    for (int off = 16; off > 0; off >>= 1) {
        sq += __shfl_down_sync(0xFFFFFFFFu, sq, off);
        float omx = __shfl_down_sync(0xFFFFFFFFu, mx, off);
        int   omi = __shfl_down_sync(0xFFFFFFFFu, mi, off);
        if (omx > mx || (omx == mx && omi < mi)) { mx = omx; mi = omi; }
    }

    __shared__ float s_sq[8];
    __shared__ float s_mx[8];
    __shared__ int   s_mi[8];
    const int wid = tid >> 5, lane = tid & 31;
    if (lane == 0) { s_sq[wid] = sq; s_mx[wid] = mx; s_mi[wid] = mi; }
    __syncthreads();

    if (wid == 0) {
        sq = (lane < 8) ? s_sq[lane] : 0.0f;
        mx = (lane < 8) ? s_mx[lane] : -CUDART_INF_F;
        mi = (lane < 8) ? s_mi[lane] : 0x7FFFFFFF;
        #pragma unroll
        for (int off = 4; off > 0; off >>= 1) {
            sq += __shfl_down_sync(0xFFFFFFFFu, sq, off);
            float omx = __shfl_down_sync(0xFFFFFFFFu, mx, off);
            int   omi = __shfl_down_sync(0xFFFFFFFFu, mi, off);
            if (omx > mx || (omx == mx && omi < mi)) { mx = omx; mi = omi; }
        }

        // ---- Label-loss epilogue (fused): broadcast result to warp 0 ----
        sq = __shfl_sync(0xFFFFFFFFu, sq, 0);
        mx = __shfl_sync(0xFFFFFFFFu, mx, 0);
        mi = __shfl_sync(0xFFFFFFFFu, mi, 0);

        const float* __restrict__ lab = labels + ((size_t)b * K + k) * 11;

        // lanes 0..8: one class-channel gather each at the argmax position
        float part = 0.0f;
        if (lane < C) {
            const float v = __ldg(&lb_preds[((size_t)bs * C + lane) * HW + mi]);
            const float d = v - __ldg(&lab[lane]);
            part = d * d;
        }
        #pragma unroll
        for (int off = 8; off > 0; off >>= 1)
            part += __shfl_down_sync(0xFFFFFFFFu, part, off);

        if (lane == 0) {
            const float gx = __ldg(&lab[9]);
            const float gy = __ldg(&lab[10]);
            const bool valid = (gx >= 0.0f) && (gy >= 0.0f) &&
                               (gx < (float)H) && (gy < (float)W);
            const int x = mi / W;   // H == W == 128: pos == idx
            const int y = mi % W;
            const float dx = gx - (float)x;
            const float dy = gy - (float)y;
            const float cf = 1.0f - mx;
            const float lb = valid ? (part + dx * dx + dy * dy + cf * cf) : 0.0f;

            atomicAdd(&out[bs],      sq);  // hm_loss [B,S]
            atomicAdd(&out[BS + bs], lb);  // lb_loss [B,S]
        }
    }
}

extern "C" void kernel_launch(void* const* d_in, const int* in_sizes, int n_in,
                              void* d_out, int out_size) {
    const float* hm_preds = (const float*)d_in[0];  // [B,S,K,H,W]
    const float* lb_preds = (const float*)d_in[1];  // [B,S,C,H,W]
    const float* heatmaps = (const float*)d_in[2];  // [B,K,H,W]
    const float* labels   = (const float*)d_in[3];  // [B,K,11]
    float* out = (float*)d_out;

    kp_zero_kernel<<<1, 2 * BS>>>(out);
    kp_fused_kernel<<<BSK, 256>>>(hm_preds, lb_preds, heatmaps, labels, out);
}